// round 15
// baseline (speedup 1.0000x reference)
#include <cuda_runtime.h>
#include <math.h>

#define NBINS  8192
#define TOPK   2048
#define CAND   3072
#define SORTN  2048
#define NPROP  1000
#define MAXB   4
#define TILES  528          // 32*33/2 upper-triangle 64x64 tiles
#define BINBUF (1 << 20)    // worst-case: whole array in one coarse bin

// ---------------- scratch (device globals; no allocation allowed) ----------
__device__ unsigned int       g_hist[MAXB][NBINS];
__device__ unsigned int       g_done[MAXB];
__device__ unsigned int       g_done2[MAXB];
__device__ unsigned int       g_bin[MAXB];
__device__ unsigned int       g_need[MAXB];
__device__ int                g_cnt[MAXB];
__device__ int                g_bcnt[MAXB];
__device__ unsigned long long g_cand[MAXB][CAND];
__device__ unsigned long long g_binbuf[MAXB][BINBUF];
__device__ float4             g_boxes[MAXB][TOPK];
__device__ float              g_area[MAXB][TOPK];
__device__ unsigned long long g_mask[MAXB][TOPK * 32];
__device__ unsigned long long g_diag[MAXB][TOPK];    // premasked diag rows
__device__ unsigned int       g_rowmask[MAXB][64];   // per word-block occupancy

__device__ __forceinline__ unsigned long long make_key(unsigned int bits, int i) {
    return ((unsigned long long)bits << 20) |
           (unsigned long long)(0xFFFFFu - (unsigned int)i);
}

// ---------------- hist over score bits + last-block resolve (ILP-8) ---------
__global__ void hist_pass(const float4* __restrict__ probs4, int N2) {
    __shared__ unsigned int sh[NBINS];
    __shared__ unsigned int s_scan[256];
    __shared__ unsigned int s_bin, s_need, s_last;
    int b = blockIdx.y;
    for (int i = threadIdx.x; i < NBINS; i += blockDim.x) sh[i] = 0;
    __syncthreads();
    const float4* p = probs4 + (size_t)b * N2;
    int stride = gridDim.x * blockDim.x;
    int i0 = blockIdx.x * blockDim.x + threadIdx.x;
    for (int i = i0; i < N2; i += 8 * stride) {
        float4 v[8]; bool ok[8];
        #pragma unroll
        for (int s = 0; s < 8; s++) {
            int ii = i + s * stride;
            ok[s] = ii < N2;
            v[s] = __ldg(p + (ok[s] ? ii : 0));
        }
        #pragma unroll
        for (int s = 0; s < 8; s++) {
            if (ok[s]) {
                atomicAdd(&sh[__float_as_uint(v[s].y) >> 19], 1u);
                atomicAdd(&sh[__float_as_uint(v[s].w) >> 19], 1u);
            }
        }
    }
    __syncthreads();
    for (int i = threadIdx.x; i < NBINS; i += blockDim.x)
        if (sh[i]) atomicAdd(&g_hist[b][i], sh[i]);

    __threadfence();
    __syncthreads();
    if (threadIdx.x == 0) {
        unsigned int ticket = atomicAdd(&g_done[b], 1u);
        s_last = (ticket == gridDim.x - 1) ? 1u : 0u;
    }
    __syncthreads();
    if (!s_last) return;
    __threadfence();

    int t = threadIdx.x;   // 256
    int base = NBINS - 1 - t * 32;
    unsigned int cnts[32];
    unsigned int sum = 0;
    #pragma unroll
    for (int m = 0; m < 32; m++) { cnts[m] = g_hist[b][base - m]; sum += cnts[m]; }
    s_scan[t] = sum;
    __syncthreads();
    for (int off = 1; off < 256; off <<= 1) {
        unsigned int v = (t >= off) ? s_scan[t - off] : 0u;
        __syncthreads();
        s_scan[t] += v;
        __syncthreads();
    }
    const unsigned int k = TOPK;
    unsigned int incl = s_scan[t];
    unsigned int excl = incl - sum;
    if (excl < k && k <= incl) {
        unsigned int cum = excl;
        #pragma unroll
        for (int m = 0; m < 32; m++) {
            if (cum + cnts[m] >= k) { s_bin = (unsigned int)(base - m);
                                      s_need = k - cum; break; }
            cum += cnts[m];
        }
    }
    __syncthreads();
    if (t == 0) {
        g_bin[b]  = s_bin;
        g_need[b] = s_need;
        g_cnt[b]  = 0;
        g_bcnt[b] = 0;
        g_done[b] = 0;
    }
    #pragma unroll
    for (int m = 0; m < 32; m++) g_hist[b][base - m] = 0;
}

// ---------------- warp-aggregated append ------------------------------------
__device__ __forceinline__ int warp_append(int* counter, bool pred) {
    unsigned int bal = __ballot_sync(0xFFFFFFFFu, pred);
    int n = __popc(bal);
    int base = 0;
    if (n) {
        int leader = __ffs(bal) - 1;
        if ((int)(threadIdx.x & 31) == leader) base = atomicAdd(counter, n);
        base = __shfl_sync(0xFFFFFFFFu, base, leader);
    }
    return base + __popc(bal & ((1u << (threadIdx.x & 31)) - 1u));
}

// ------- fused: partition (all blocks) + exact refine+sort+decode (last) ----
__global__ void __launch_bounds__(1024)
partition_refine_sort(const float4* __restrict__ probs4, int N2,
                      const float4* __restrict__ bbox,
                      const float4* __restrict__ anchors, int N) {
    __shared__ unsigned long long sk[SORTN];     // 16 KB sort array
    __shared__ unsigned int shist[NBINS];        // 32 KB refine hist
    __shared__ unsigned int s_warp[32];
    __shared__ unsigned int s_bin, s_need, s_last;
    __shared__ int s_cnt;

    int b = blockIdx.y;
    int t = threadIdx.x;      // 1024
    int lane = t & 31, wid = t >> 5;

    // ---- phase A: partition scan (ILP-8) ----
    {
        unsigned int Tbin = g_bin[b];
        const float4* p = probs4 + (size_t)b * N2;
        int stride = gridDim.x * blockDim.x;
        int i0 = blockIdx.x * blockDim.x + t;
        for (int i = i0; i < N2; i += 8 * stride) {
            float4 v[8]; bool ok[8]; int iic[8];
            #pragma unroll
            for (int s = 0; s < 8; s++) {
                int ii = i + s * stride;
                ok[s] = ii < N2;
                iic[s] = ok[s] ? ii : 0;
                v[s] = __ldg(p + iic[s]);
            }
            #pragma unroll
            for (int s = 0; s < 8; s++) {
                unsigned int b0 = __float_as_uint(v[s].y);
                unsigned int b1 = __float_as_uint(v[s].w);
                unsigned int bin0 = b0 >> 19, bin1 = b1 >> 19;

                bool c0 = ok[s] && (bin0 > Tbin);
                int pos = warp_append(&g_cnt[b], c0);
                if (c0 && pos < CAND) g_cand[b][pos] = make_key(b0, 2 * iic[s]);

                bool d0 = ok[s] && (bin0 == Tbin);
                pos = warp_append(&g_bcnt[b], d0);
                if (d0 && pos < BINBUF) g_binbuf[b][pos] = make_key(b0, 2 * iic[s]);

                bool c1 = ok[s] && (bin1 > Tbin);
                pos = warp_append(&g_cnt[b], c1);
                if (c1 && pos < CAND) g_cand[b][pos] = make_key(b1, 2 * iic[s] + 1);

                bool d1 = ok[s] && (bin1 == Tbin);
                pos = warp_append(&g_bcnt[b], d1);
                if (d1 && pos < BINBUF) g_binbuf[b][pos] = make_key(b1, 2 * iic[s] + 1);
            }
        }
    }

    // ---- ticket: last block of this batch continues ----
    __threadfence();
    __syncthreads();
    if (t == 0) {
        unsigned int ticket = atomicAdd(&g_done2[b], 1u);
        s_last = (ticket == gridDim.x - 1) ? 1u : 0u;
    }
    __syncthreads();
    if (!s_last) return;
    __threadfence();

    int n = g_bcnt[b];    if (n > BINBUF) n = BINBUF;
    int acnt = g_cnt[b];  if (acnt > CAND) acnt = CAND;
    if (t == 0) { g_done2[b] = 0; s_need = g_need[b]; }
    __syncthreads();

    // ---- phase B: 3-pass exact refine over low 39 key bits ----
    const unsigned long long M39 = (1ULL << 39) - 1ULL;
    unsigned long long prefix = 0ULL;
    for (int pass = 0; pass < 3; pass++) {
        int shift = 26 - 13 * pass;
        for (int i = t; i < NBINS; i += 1024) shist[i] = 0;
        __syncthreads();
        for (int i = t; i < n; i += 1024) {
            unsigned long long k39 = g_binbuf[b][i] & M39;
            if ((k39 >> (shift + 13)) == prefix)
                atomicAdd(&shist[(unsigned int)(k39 >> shift) & (NBINS - 1)], 1u);
        }
        __syncthreads();
        int base = NBINS - 1 - t * 8;
        unsigned int c8[8];
        unsigned int sum = 0;
        #pragma unroll
        for (int m = 0; m < 8; m++) { c8[m] = shist[base - m]; sum += c8[m]; }
        unsigned int v = sum;
        #pragma unroll
        for (int off = 1; off < 32; off <<= 1) {
            unsigned int u = __shfl_up_sync(0xFFFFFFFFu, v, off);
            if (lane >= off) v += u;
        }
        if (lane == 31) s_warp[wid] = v;
        __syncthreads();
        if (wid == 0) {
            unsigned int w = s_warp[lane];
            #pragma unroll
            for (int off = 1; off < 32; off <<= 1) {
                unsigned int u = __shfl_up_sync(0xFFFFFFFFu, w, off);
                if (lane >= off) w += u;
            }
            s_warp[lane] = w;
        }
        __syncthreads();
        unsigned int need = s_need;
        unsigned int woff = (wid > 0) ? s_warp[wid - 1] : 0u;
        unsigned int incl = v + woff;
        unsigned int excl = incl - sum;
        if (excl < need && need <= incl) {
            unsigned int cum = excl;
            #pragma unroll
            for (int m = 0; m < 8; m++) {
                if (cum + c8[m] >= need) {
                    s_bin  = (unsigned int)(base - m);
                    s_need = need - cum;
                    break;
                }
                cum += c8[m];
            }
        }
        __syncthreads();
        prefix = (prefix << 13) | (unsigned long long)s_bin;
        __syncthreads();
    }
    unsigned long long thr = prefix;

    // ---- phase C: build exactly-2048 sort array ----
    for (int i = t; i < SORTN; i += 1024) sk[i] = 0ULL;
    if (t == 0) s_cnt = acnt;
    __syncthreads();
    for (int i = t; i < acnt; i += 1024) sk[i] = g_cand[b][i];
    int npad = ((n + 1023) / 1024) * 1024;
    for (int i = t; i < npad; i += 1024) {
        bool ok = i < n;
        unsigned long long kk = ok ? g_binbuf[b][i] : 0ULL;
        bool pred = ok && ((kk & M39) >= thr);
        int pos = warp_append(&s_cnt, pred);
        if (pred && pos < SORTN) sk[pos] = kk;
    }
    __syncthreads();

    // ---- phase D: bitonic sort 2048 ----
    for (int k = 2; k <= SORTN; k <<= 1) {
        for (int j = k >> 1; j > 0; j >>= 1) {
            #pragma unroll
            for (int s = 0; s < 2; s++) {
                int i = t + s * 1024;
                int l = i ^ j;
                if (l > i) {
                    bool up = ((i & k) == 0);
                    unsigned long long a = sk[i], c = sk[l];
                    if ((a > c) == up) { sk[i] = c; sk[l] = a; }
                }
            }
            __syncthreads();
        }
    }

    // ---- phase E: decode top 2048 ----
    const float4* bb = bbox    + (size_t)b * N;
    const float4* an = anchors + (size_t)b * N;
    #pragma unroll
    for (int s = 0; s < 2; s++) {
        int r = t + s * 1024;
        unsigned long long key = sk[SORTN - 1 - r];
        int idx = 0xFFFFF - (int)(key & 0xFFFFFULL);
        float4 a = an[idx];
        float4 d = bb[idx];
        float d0 = __fmul_rn(d.x, 0.1f), d1 = __fmul_rn(d.y, 0.1f);
        float d2 = __fmul_rn(d.z, 0.2f), d3 = __fmul_rn(d.w, 0.2f);
        float h = __fsub_rn(a.z, a.x);
        float w = __fsub_rn(a.w, a.y);
        float cy = __fadd_rn(__fadd_rn(a.x, __fmul_rn(0.5f, h)), __fmul_rn(d0, h));
        float cx = __fadd_rn(__fadd_rn(a.y, __fmul_rn(0.5f, w)), __fmul_rn(d1, w));
        float e2 = (float)exp((double)d2);
        float e3 = (float)exp((double)d3);
        float h2 = __fmul_rn(h, e2);
        float w2 = __fmul_rn(w, e3);
        float y1 = __fsub_rn(cy, __fmul_rn(0.5f, h2));
        float x1 = __fsub_rn(cx, __fmul_rn(0.5f, w2));
        float y2 = __fadd_rn(cy, __fmul_rn(0.5f, h2));
        float x2 = __fadd_rn(cx, __fmul_rn(0.5f, w2));
        y1 = fminf(fmaxf(y1, 0.0f), 1.0f);
        x1 = fminf(fmaxf(x1, 0.0f), 1.0f);
        y2 = fminf(fmaxf(y2, 0.0f), 1.0f);
        x2 = fminf(fmaxf(x2, 0.0f), 1.0f);
        g_boxes[b][r] = make_float4(y1, x1, y2, x2);
        g_area[b][r]  = __fmul_rn(__fsub_rn(y2, y1), __fsub_rn(x2, x1));
    }
}

// ---------------- pairwise IoU > 0.7 bitmask + premasked diag + occupancy ---
__global__ void mask_kernel() {
    int b = blockIdx.y;
    int tt = blockIdx.x;
    int ib = 0, acc = 0;
    while (acc + (32 - ib) <= tt) { acc += 32 - ib; ib++; }
    int jb = ib + (tt - acc);

    __shared__ float4 sj[64];
    __shared__ float  sa[64];
    int t = threadIdx.x;   // 64
    sj[t] = g_boxes[b][jb * 64 + t];
    sa[t] = g_area[b][jb * 64 + t];
    __syncthreads();
    int i = ib * 64 + t;
    float4 bi = g_boxes[b][i];
    float areai = g_area[b][i];
    unsigned long long bits = 0ULL;
    #pragma unroll 8
    for (int jj = 0; jj < 64; jj++) {
        float4 bj = sj[jj];
        float ih = fmaxf(__fsub_rn(fminf(bi.z, bj.z), fmaxf(bi.x, bj.x)), 0.0f);
        float iw = fmaxf(__fsub_rn(fminf(bi.w, bj.w), fmaxf(bi.y, bj.y)), 0.0f);
        float inter = __fmul_rn(ih, iw);
        float uni = __fsub_rn(__fadd_rn(areai, sa[jj]), inter);
        float den = __fadd_rn(uni, 1e-8f);
        if (inter > 0.68f * den) {            // conservative prefilter
            float iou = __fdiv_rn(inter, den);
            if (iou > 0.7f) bits |= (1ULL << jj);
        }
    }
    g_mask[b][(size_t)i * 32 + jb] = bits;

    // diag blocks: premasked row word ("suppresses strictly later bits only")
    unsigned long long prem = bits & ((t < 63) ? (~0ULL << (t + 1)) : 0ULL);
    unsigned int flag = (ib == jb && prem != 0ULL) ? 1u : 0u;
    unsigned int bal = __ballot_sync(0xFFFFFFFFu, flag != 0u);
    if (ib == jb) {
        g_diag[b][ib * 64 + t] = prem;
        if ((t & 31) == 0)
            g_rowmask[b][ib * 2 + (t >> 5)] = bal;   // rows 0-31 / 32-63
    }
}

// ------- one-warp NMS: sparse chain on smem diag, supp via direct LDG -------
__global__ void __launch_bounds__(32) nms_kernel(float* __restrict__ out) {
    int b = blockIdx.x;
    int t = threadIdx.x;   // 32 (one warp)
    __shared__ unsigned long long sdiag[TOPK];     // 16 KB premasked diag rows
    __shared__ unsigned long long srm[32];

    float4* o4 = (float4*)(out + (size_t)b * NPROP * 4);
    for (int k = t; k < NPROP; k += 32) o4[k] = make_float4(0.f, 0.f, 0.f, 0.f);

    // stage all diag rows once (coalesced) + row-occupancy masks
    for (int i = t; i < TOPK; i += 32) sdiag[i] = __ldg(&g_diag[b][i]);
    {
        unsigned int lo = g_rowmask[b][t * 2];
        unsigned int hi = g_rowmask[b][t * 2 + 1];
        srm[t] = ((unsigned long long)hi << 32) | lo;
    }
    __syncwarp();

    const unsigned long long* mb = g_mask[b];
    unsigned long long keepw = ~0ULL;      // lane t owns bits [t*64, t*64+64)

    for (int c = 0; c < 32; c++) {
        // ---- sparse within-word chain (all lanes redundant, uniform) ----
        unsigned long long cur = __shfl_sync(0xFFFFFFFFu, keepw, c);
        unsigned long long w = cur & srm[c];
        const unsigned long long* dg = &sdiag[c * 64];
        while (w) {
            int bit = __ffsll((long long)w) - 1;
            w &= w - 1;
            cur &= ~dg[bit];          // premasked: suppress strictly-later bits
            w &= cur;
        }
        // cur identical on all lanes (uniform data, uniform control)

        // ---- cross-word suppression: direct LDG, 4 independent accumulators -
        const unsigned long long* col = mb + (size_t)(c * 64) * 32 + t;
        unsigned long long s0 = 0ULL, s1 = 0ULL, s2 = 0ULL, s3 = 0ULL;
        #pragma unroll
        for (int r = 0; r < 64; r += 4) {
            unsigned long long m0 = __ldg(col + (size_t)(r + 0) * 32);
            unsigned long long m1 = __ldg(col + (size_t)(r + 1) * 32);
            unsigned long long m2 = __ldg(col + (size_t)(r + 2) * 32);
            unsigned long long m3 = __ldg(col + (size_t)(r + 3) * 32);
            unsigned long long e0 =
                (unsigned long long)((long long)(cur << (63 - r)) >> 63);
            unsigned long long e1 =
                (unsigned long long)((long long)(cur << (62 - r)) >> 63);
            unsigned long long e2 =
                (unsigned long long)((long long)(cur << (61 - r)) >> 63);
            unsigned long long e3 =
                (unsigned long long)((long long)(cur << (60 - r)) >> 63);
            s0 |= m0 & e0;
            s1 |= m1 & e1;
            s2 |= m2 & e2;
            s3 |= m3 & e3;
        }
        unsigned long long supp = (s0 | s1) | (s2 | s3);

        if (t == c)      keepw = cur;
        else if (t > c)  keepw &= ~supp;
        __syncwarp();
    }

    // exclusive prefix of popcounts across lanes
    int pc = __popcll(keepw);
    int ex = pc;
    #pragma unroll
    for (int off = 1; off < 32; off <<= 1) {
        int v = __shfl_up_sync(0xFFFFFFFFu, ex, off);
        if (t >= off) ex += v;
    }
    ex -= pc;

    for (int bit = 0; bit < 64; bit++) {
        if ((keepw >> bit) & 1ULL) {
            unsigned long long lower = (bit > 0) ? (keepw & ((1ULL << bit) - 1ULL)) : 0ULL;
            int rank = ex + __popcll(lower);
            if (rank < NPROP) {
                float4 bx = g_boxes[b][t * 64 + bit];
                float* o = out + ((size_t)b * NPROP + rank) * 4;
                o[0] = bx.x; o[1] = bx.y; o[2] = bx.z; o[3] = bx.w;
            }
        }
    }
}

// ---------------- launch ----------------------------------------------------
extern "C" void kernel_launch(void* const* d_in, const int* in_sizes, int n_in,
                              void* d_out, int out_size) {
    const float4* probs4  = (const float4*)d_in[0];
    const float4* bbox    = (const float4*)d_in[1];
    const float4* anchors = (const float4*)d_in[2];
    float* out = (float*)d_out;

    int B = out_size / (NPROP * 4);
    if (B < 1) B = 1;
    if (B > MAXB) B = MAXB;
    int N  = in_sizes[0] / (2 * B);
    int N2 = N / 2;

    hist_pass<<<dim3(256, B), 256>>>(probs4, N2);
    partition_refine_sort<<<dim3(64, B), 1024>>>(probs4, N2, bbox, anchors, N);
    mask_kernel<<<dim3(TILES, B), 64>>>();
    nms_kernel<<<B, 32>>>(out);
}

// round 16
// speedup vs baseline: 1.0396x; 1.0396x over previous
#include <cuda_runtime.h>
#include <math.h>

#define NBINS  8192
#define TOPK   2048
#define CAND   3072
#define SORTN  2048
#define NPROP  1000
#define MAXB   4
#define TILES  528          // 32*33/2 upper-triangle 64x64 tiles
#define BINBUF (1 << 20)    // worst-case: whole array in one coarse bin

// ---------------- scratch (device globals; no allocation allowed) ----------
__device__ unsigned int       g_hist[MAXB][NBINS];
__device__ unsigned int       g_done[MAXB];
__device__ unsigned int       g_done2[MAXB];
__device__ unsigned int       g_bin[MAXB];
__device__ unsigned int       g_need[MAXB];
__device__ int                g_cnt[MAXB];
__device__ int                g_bcnt[MAXB];
__device__ unsigned long long g_cand[MAXB][CAND];
__device__ unsigned long long g_binbuf[MAXB][BINBUF];
__device__ float4             g_boxes[MAXB][TOPK];
__device__ float              g_area[MAXB][TOPK];
__device__ unsigned long long g_mask[MAXB][TOPK * 32];
__device__ unsigned long long g_diag[MAXB][TOPK];    // premasked diag rows
__device__ unsigned int       g_rowmask[MAXB][64];   // per word-block occupancy

__device__ __forceinline__ unsigned long long make_key(unsigned int bits, int i) {
    return ((unsigned long long)bits << 20) |
           (unsigned long long)(0xFFFFFu - (unsigned int)i);
}

// ---------------- hist over score bits + last-block resolve (ILP-8) ---------
__global__ void hist_pass(const float4* __restrict__ probs4, int N2) {
    __shared__ unsigned int sh[NBINS];
    __shared__ unsigned int s_scan[256];
    __shared__ unsigned int s_bin, s_need, s_last;
    int b = blockIdx.y;
    for (int i = threadIdx.x; i < NBINS; i += blockDim.x) sh[i] = 0;
    __syncthreads();
    const float4* p = probs4 + (size_t)b * N2;
    int stride = gridDim.x * blockDim.x;
    int i0 = blockIdx.x * blockDim.x + threadIdx.x;
    for (int i = i0; i < N2; i += 8 * stride) {
        float4 v[8]; bool ok[8];
        #pragma unroll
        for (int s = 0; s < 8; s++) {
            int ii = i + s * stride;
            ok[s] = ii < N2;
            v[s] = __ldg(p + (ok[s] ? ii : 0));
        }
        #pragma unroll
        for (int s = 0; s < 8; s++) {
            if (ok[s]) {
                atomicAdd(&sh[__float_as_uint(v[s].y) >> 19], 1u);
                atomicAdd(&sh[__float_as_uint(v[s].w) >> 19], 1u);
            }
        }
    }
    __syncthreads();
    for (int i = threadIdx.x; i < NBINS; i += blockDim.x)
        if (sh[i]) atomicAdd(&g_hist[b][i], sh[i]);

    __threadfence();
    __syncthreads();
    if (threadIdx.x == 0) {
        unsigned int ticket = atomicAdd(&g_done[b], 1u);
        s_last = (ticket == gridDim.x - 1) ? 1u : 0u;
    }
    __syncthreads();
    if (!s_last) return;
    __threadfence();

    int t = threadIdx.x;   // 256
    int base = NBINS - 1 - t * 32;
    unsigned int cnts[32];
    unsigned int sum = 0;
    #pragma unroll
    for (int m = 0; m < 32; m++) { cnts[m] = g_hist[b][base - m]; sum += cnts[m]; }
    s_scan[t] = sum;
    __syncthreads();
    for (int off = 1; off < 256; off <<= 1) {
        unsigned int v = (t >= off) ? s_scan[t - off] : 0u;
        __syncthreads();
        s_scan[t] += v;
        __syncthreads();
    }
    const unsigned int k = TOPK;
    unsigned int incl = s_scan[t];
    unsigned int excl = incl - sum;
    if (excl < k && k <= incl) {
        unsigned int cum = excl;
        #pragma unroll
        for (int m = 0; m < 32; m++) {
            if (cum + cnts[m] >= k) { s_bin = (unsigned int)(base - m);
                                      s_need = k - cum; break; }
            cum += cnts[m];
        }
    }
    __syncthreads();
    if (t == 0) {
        g_bin[b]  = s_bin;
        g_need[b] = s_need;
        g_cnt[b]  = 0;
        g_bcnt[b] = 0;
        g_done[b] = 0;
    }
    #pragma unroll
    for (int m = 0; m < 32; m++) g_hist[b][base - m] = 0;
}

// ---------------- warp-aggregated append ------------------------------------
__device__ __forceinline__ int warp_append(int* counter, bool pred) {
    unsigned int bal = __ballot_sync(0xFFFFFFFFu, pred);
    int n = __popc(bal);
    int base = 0;
    if (n) {
        int leader = __ffs(bal) - 1;
        if ((int)(threadIdx.x & 31) == leader) base = atomicAdd(counter, n);
        base = __shfl_sync(0xFFFFFFFFu, base, leader);
    }
    return base + __popc(bal & ((1u << (threadIdx.x & 31)) - 1u));
}

// ------- fused: partition (all blocks) + exact refine+sort+decode (last) ----
__global__ void __launch_bounds__(1024)
partition_refine_sort(const float4* __restrict__ probs4, int N2,
                      const float4* __restrict__ bbox,
                      const float4* __restrict__ anchors, int N) {
    __shared__ unsigned long long sk[SORTN];     // 16 KB sort array
    __shared__ unsigned int shist[NBINS];        // 32 KB refine hist
    __shared__ unsigned int s_warp[32];
    __shared__ unsigned int s_bin, s_need, s_last;
    __shared__ int s_cnt;

    int b = blockIdx.y;
    int t = threadIdx.x;      // 1024
    int lane = t & 31, wid = t >> 5;

    // ---- phase A: partition scan (ILP-8) ----
    {
        unsigned int Tbin = g_bin[b];
        const float4* p = probs4 + (size_t)b * N2;
        int stride = gridDim.x * blockDim.x;
        int i0 = blockIdx.x * blockDim.x + t;
        for (int i = i0; i < N2; i += 8 * stride) {
            float4 v[8]; bool ok[8]; int iic[8];
            #pragma unroll
            for (int s = 0; s < 8; s++) {
                int ii = i + s * stride;
                ok[s] = ii < N2;
                iic[s] = ok[s] ? ii : 0;
                v[s] = __ldg(p + iic[s]);
            }
            #pragma unroll
            for (int s = 0; s < 8; s++) {
                unsigned int b0 = __float_as_uint(v[s].y);
                unsigned int b1 = __float_as_uint(v[s].w);
                unsigned int bin0 = b0 >> 19, bin1 = b1 >> 19;

                bool c0 = ok[s] && (bin0 > Tbin);
                int pos = warp_append(&g_cnt[b], c0);
                if (c0 && pos < CAND) g_cand[b][pos] = make_key(b0, 2 * iic[s]);

                bool d0 = ok[s] && (bin0 == Tbin);
                pos = warp_append(&g_bcnt[b], d0);
                if (d0 && pos < BINBUF) g_binbuf[b][pos] = make_key(b0, 2 * iic[s]);

                bool c1 = ok[s] && (bin1 > Tbin);
                pos = warp_append(&g_cnt[b], c1);
                if (c1 && pos < CAND) g_cand[b][pos] = make_key(b1, 2 * iic[s] + 1);

                bool d1 = ok[s] && (bin1 == Tbin);
                pos = warp_append(&g_bcnt[b], d1);
                if (d1 && pos < BINBUF) g_binbuf[b][pos] = make_key(b1, 2 * iic[s] + 1);
            }
        }
    }

    // ---- ticket: last block of this batch continues ----
    __threadfence();
    __syncthreads();
    if (t == 0) {
        unsigned int ticket = atomicAdd(&g_done2[b], 1u);
        s_last = (ticket == gridDim.x - 1) ? 1u : 0u;
    }
    __syncthreads();
    if (!s_last) return;
    __threadfence();

    int n = g_bcnt[b];    if (n > BINBUF) n = BINBUF;
    int acnt = g_cnt[b];  if (acnt > CAND) acnt = CAND;
    if (t == 0) { g_done2[b] = 0; s_need = g_need[b]; }
    __syncthreads();

    // ---- phase B: 3-pass exact refine over low 39 key bits ----
    const unsigned long long M39 = (1ULL << 39) - 1ULL;
    unsigned long long prefix = 0ULL;
    for (int pass = 0; pass < 3; pass++) {
        int shift = 26 - 13 * pass;
        for (int i = t; i < NBINS; i += 1024) shist[i] = 0;
        __syncthreads();
        for (int i = t; i < n; i += 1024) {
            unsigned long long k39 = g_binbuf[b][i] & M39;
            if ((k39 >> (shift + 13)) == prefix)
                atomicAdd(&shist[(unsigned int)(k39 >> shift) & (NBINS - 1)], 1u);
        }
        __syncthreads();
        int base = NBINS - 1 - t * 8;
        unsigned int c8[8];
        unsigned int sum = 0;
        #pragma unroll
        for (int m = 0; m < 8; m++) { c8[m] = shist[base - m]; sum += c8[m]; }
        unsigned int v = sum;
        #pragma unroll
        for (int off = 1; off < 32; off <<= 1) {
            unsigned int u = __shfl_up_sync(0xFFFFFFFFu, v, off);
            if (lane >= off) v += u;
        }
        if (lane == 31) s_warp[wid] = v;
        __syncthreads();
        if (wid == 0) {
            unsigned int w = s_warp[lane];
            #pragma unroll
            for (int off = 1; off < 32; off <<= 1) {
                unsigned int u = __shfl_up_sync(0xFFFFFFFFu, w, off);
                if (lane >= off) w += u;
            }
            s_warp[lane] = w;
        }
        __syncthreads();
        unsigned int need = s_need;
        unsigned int woff = (wid > 0) ? s_warp[wid - 1] : 0u;
        unsigned int incl = v + woff;
        unsigned int excl = incl - sum;
        if (excl < need && need <= incl) {
            unsigned int cum = excl;
            #pragma unroll
            for (int m = 0; m < 8; m++) {
                if (cum + c8[m] >= need) {
                    s_bin  = (unsigned int)(base - m);
                    s_need = need - cum;
                    break;
                }
                cum += c8[m];
            }
        }
        __syncthreads();
        prefix = (prefix << 13) | (unsigned long long)s_bin;
        __syncthreads();
    }
    unsigned long long thr = prefix;

    // ---- phase C: build exactly-2048 sort array ----
    for (int i = t; i < SORTN; i += 1024) sk[i] = 0ULL;
    if (t == 0) s_cnt = acnt;
    __syncthreads();
    for (int i = t; i < acnt; i += 1024) sk[i] = g_cand[b][i];
    int npad = ((n + 1023) / 1024) * 1024;
    for (int i = t; i < npad; i += 1024) {
        bool ok = i < n;
        unsigned long long kk = ok ? g_binbuf[b][i] : 0ULL;
        bool pred = ok && ((kk & M39) >= thr);
        int pos = warp_append(&s_cnt, pred);
        if (pred && pos < SORTN) sk[pos] = kk;
    }
    __syncthreads();

    // ---- phase D: bitonic sort 2048 ----
    for (int k = 2; k <= SORTN; k <<= 1) {
        for (int j = k >> 1; j > 0; j >>= 1) {
            #pragma unroll
            for (int s = 0; s < 2; s++) {
                int i = t + s * 1024;
                int l = i ^ j;
                if (l > i) {
                    bool up = ((i & k) == 0);
                    unsigned long long a = sk[i], c = sk[l];
                    if ((a > c) == up) { sk[i] = c; sk[l] = a; }
                }
            }
            __syncthreads();
        }
    }

    // ---- phase E: decode top 2048 ----
    const float4* bb = bbox    + (size_t)b * N;
    const float4* an = anchors + (size_t)b * N;
    #pragma unroll
    for (int s = 0; s < 2; s++) {
        int r = t + s * 1024;
        unsigned long long key = sk[SORTN - 1 - r];
        int idx = 0xFFFFF - (int)(key & 0xFFFFFULL);
        float4 a = an[idx];
        float4 d = bb[idx];
        float d0 = __fmul_rn(d.x, 0.1f), d1 = __fmul_rn(d.y, 0.1f);
        float d2 = __fmul_rn(d.z, 0.2f), d3 = __fmul_rn(d.w, 0.2f);
        float h = __fsub_rn(a.z, a.x);
        float w = __fsub_rn(a.w, a.y);
        float cy = __fadd_rn(__fadd_rn(a.x, __fmul_rn(0.5f, h)), __fmul_rn(d0, h));
        float cx = __fadd_rn(__fadd_rn(a.y, __fmul_rn(0.5f, w)), __fmul_rn(d1, w));
        float e2 = (float)exp((double)d2);
        float e3 = (float)exp((double)d3);
        float h2 = __fmul_rn(h, e2);
        float w2 = __fmul_rn(w, e3);
        float y1 = __fsub_rn(cy, __fmul_rn(0.5f, h2));
        float x1 = __fsub_rn(cx, __fmul_rn(0.5f, w2));
        float y2 = __fadd_rn(cy, __fmul_rn(0.5f, h2));
        float x2 = __fadd_rn(cx, __fmul_rn(0.5f, w2));
        y1 = fminf(fmaxf(y1, 0.0f), 1.0f);
        x1 = fminf(fmaxf(x1, 0.0f), 1.0f);
        y2 = fminf(fmaxf(y2, 0.0f), 1.0f);
        x2 = fminf(fmaxf(x2, 0.0f), 1.0f);
        g_boxes[b][r] = make_float4(y1, x1, y2, x2);
        g_area[b][r]  = __fmul_rn(__fsub_rn(y2, y1), __fsub_rn(x2, x1));
    }
}

// ---------------- pairwise IoU > 0.7 bitmask + premasked diag + occupancy ---
__global__ void mask_kernel() {
    int b = blockIdx.y;
    int tt = blockIdx.x;
    int ib = 0, acc = 0;
    while (acc + (32 - ib) <= tt) { acc += 32 - ib; ib++; }
    int jb = ib + (tt - acc);

    __shared__ float4 sj[64];
    __shared__ float  sa[64];
    int t = threadIdx.x;   // 64
    sj[t] = g_boxes[b][jb * 64 + t];
    sa[t] = g_area[b][jb * 64 + t];
    __syncthreads();
    int i = ib * 64 + t;
    float4 bi = g_boxes[b][i];
    float areai = g_area[b][i];
    unsigned long long bits = 0ULL;
    #pragma unroll 8
    for (int jj = 0; jj < 64; jj++) {
        float4 bj = sj[jj];
        float ih = fmaxf(__fsub_rn(fminf(bi.z, bj.z), fmaxf(bi.x, bj.x)), 0.0f);
        float iw = fmaxf(__fsub_rn(fminf(bi.w, bj.w), fmaxf(bi.y, bj.y)), 0.0f);
        float inter = __fmul_rn(ih, iw);
        float uni = __fsub_rn(__fadd_rn(areai, sa[jj]), inter);
        float den = __fadd_rn(uni, 1e-8f);
        if (inter > 0.68f * den) {            // conservative prefilter
            float iou = __fdiv_rn(inter, den);
            if (iou > 0.7f) bits |= (1ULL << jj);
        }
    }
    g_mask[b][(size_t)i * 32 + jb] = bits;

    // diag blocks: premasked row word ("suppresses strictly later bits only")
    unsigned long long prem = bits & ((t < 63) ? (~0ULL << (t + 1)) : 0ULL);
    unsigned int flag = (ib == jb && prem != 0ULL) ? 1u : 0u;
    unsigned int bal = __ballot_sync(0xFFFFFFFFu, flag != 0u);
    if (ib == jb) {
        g_diag[b][ib * 64 + t] = prem;
        if ((t & 31) == 0)
            g_rowmask[b][ib * 2 + (t >> 5)] = bal;   // rows 0-31 / 32-63
    }
}

// --- one-warp NMS: sparse chain on pre-staged diag (overlapped with the
//     cp.async transfer of the current block), smem-staged supp --------------
__global__ void __launch_bounds__(32) nms_kernel(float* __restrict__ out) {
    int b = blockIdx.x;
    int t = threadIdx.x;   // 32 (one warp)
    __shared__ unsigned long long sbuf[2][2048];   // 2 x 16KB mask blocks
    __shared__ unsigned long long sdiag[TOPK];     // 16KB premasked diag rows
    __shared__ unsigned long long srm[32];

    float4* o4 = (float4*)(out + (size_t)b * NPROP * 4);
    for (int k = t; k < NPROP; k += 32) o4[k] = make_float4(0.f, 0.f, 0.f, 0.f);

    const unsigned long long* mb = g_mask[b];

    {   // prefetch block 0 first (gets the transfer going early)
        const char* src = (const char*)mb;
        char* dst = (char*)&sbuf[0][0];
        #pragma unroll
        for (int k = 0; k < 32; k++) {
            unsigned int d = (unsigned int)__cvta_generic_to_shared(dst + t * 16 + k * 512);
            asm volatile("cp.async.cg.shared.global [%0], [%1], 16;\n"
                         :: "r"(d), "l"(src + t * 16 + k * 512));
        }
        asm volatile("cp.async.commit_group;\n" ::);
    }

    // stage diag rows + occupancy while block-0 transfer is in flight
    for (int i = t; i < TOPK; i += 32) sdiag[i] = __ldg(&g_diag[b][i]);
    {
        unsigned int lo = g_rowmask[b][t * 2];
        unsigned int hi = g_rowmask[b][t * 2 + 1];
        srm[t] = ((unsigned long long)hi << 32) | lo;
    }
    __syncwarp();

    unsigned long long keepw = ~0ULL;      // lane t owns bits [t*64, t*64+64)

    for (int c = 0; c < 32; c++) {
        int cb = c & 1;

        // ---- sparse within-word chain on sdiag — no sbuf dependency, so it
        //      runs UNDER the in-flight transfer of block c ----
        unsigned long long cur = __shfl_sync(0xFFFFFFFFu, keepw, c);
        unsigned long long w = cur & srm[c];
        const unsigned long long* dg = &sdiag[c * 64];
        while (w) {
            int bit = __ffsll((long long)w) - 1;
            w &= w - 1;
            cur &= ~dg[bit];          // premasked: suppress strictly-later bits
            w &= cur;
        }
        // cur identical on all lanes (uniform data, uniform control)

        // ---- now wait for block c, then prefetch block c+1 ----
        asm volatile("cp.async.wait_group 0;\n" ::);
        __syncwarp();
        if (c + 1 < 32) {
            const char* src = (const char*)(mb + (size_t)(c + 1) * 2048);
            char* dst = (char*)&sbuf[cb ^ 1][0];
            #pragma unroll
            for (int k = 0; k < 32; k++) {
                unsigned int d = (unsigned int)__cvta_generic_to_shared(dst + t * 16 + k * 512);
                asm volatile("cp.async.cg.shared.global [%0], [%1], 16;\n"
                             :: "r"(d), "l"(src + t * 16 + k * 512));
            }
            asm volatile("cp.async.commit_group;\n" ::);
        }

        // ---- cross-word suppression: lane t's own column, 4 accumulators ---
        const unsigned long long* blk = &sbuf[cb][0];
        unsigned long long s0 = 0ULL, s1 = 0ULL, s2 = 0ULL, s3 = 0ULL;
        #pragma unroll
        for (int r = 0; r < 64; r += 4) {
            unsigned long long e0 =
                (unsigned long long)((long long)(cur << (63 - r)) >> 63);
            unsigned long long e1 =
                (unsigned long long)((long long)(cur << (62 - r)) >> 63);
            unsigned long long e2 =
                (unsigned long long)((long long)(cur << (61 - r)) >> 63);
            unsigned long long e3 =
                (unsigned long long)((long long)(cur << (60 - r)) >> 63);
            s0 |= blk[(r + 0) * 32 + t] & e0;
            s1 |= blk[(r + 1) * 32 + t] & e1;
            s2 |= blk[(r + 2) * 32 + t] & e2;
            s3 |= blk[(r + 3) * 32 + t] & e3;
        }
        unsigned long long supp = (s0 | s1) | (s2 | s3);

        if (t == c)      keepw = cur;
        else if (t > c)  keepw &= ~supp;
        __syncwarp();
    }

    // exclusive prefix of popcounts across lanes
    int pc = __popcll(keepw);
    int ex = pc;
    #pragma unroll
    for (int off = 1; off < 32; off <<= 1) {
        int v = __shfl_up_sync(0xFFFFFFFFu, ex, off);
        if (t >= off) ex += v;
    }
    ex -= pc;

    for (int bit = 0; bit < 64; bit++) {
        if ((keepw >> bit) & 1ULL) {
            unsigned long long lower = (bit > 0) ? (keepw & ((1ULL << bit) - 1ULL)) : 0ULL;
            int rank = ex + __popcll(lower);
            if (rank < NPROP) {
                float4 bx = g_boxes[b][t * 64 + bit];
                float* o = out + ((size_t)b * NPROP + rank) * 4;
                o[0] = bx.x; o[1] = bx.y; o[2] = bx.z; o[3] = bx.w;
            }
        }
    }
}

// ---------------- launch ----------------------------------------------------
extern "C" void kernel_launch(void* const* d_in, const int* in_sizes, int n_in,
                              void* d_out, int out_size) {
    const float4* probs4  = (const float4*)d_in[0];
    const float4* bbox    = (const float4*)d_in[1];
    const float4* anchors = (const float4*)d_in[2];
    float* out = (float*)d_out;

    int B = out_size / (NPROP * 4);
    if (B < 1) B = 1;
    if (B > MAXB) B = MAXB;
    int N  = in_sizes[0] / (2 * B);
    int N2 = N / 2;

    hist_pass<<<dim3(256, B), 256>>>(probs4, N2);
    partition_refine_sort<<<dim3(64, B), 1024>>>(probs4, N2, bbox, anchors, N);
    mask_kernel<<<dim3(TILES, B), 64>>>();
    nms_kernel<<<B, 32>>>(out);
}

// round 17
// speedup vs baseline: 1.1284x; 1.0854x over previous
#include <cuda_runtime.h>
#include <math.h>

#define NBINS  8192
#define TOPK   2048
#define CAND   3072
#define SORTN  2048
#define NPROP  1000
#define MAXB   4
#define TILES  528          // 32*33/2 upper-triangle 64x64 tiles
#define BINBUF (1 << 20)    // worst-case: whole array in one coarse bin

// ---------------- scratch (device globals; no allocation allowed) ----------
__device__ unsigned int       g_hist[MAXB][NBINS];
__device__ unsigned int       g_done[MAXB];
__device__ unsigned int       g_done2[MAXB];
__device__ unsigned int       g_bin[MAXB];
__device__ unsigned int       g_need[MAXB];
__device__ int                g_cnt[MAXB];
__device__ int                g_bcnt[MAXB];
__device__ unsigned long long g_cand[MAXB][CAND];
__device__ unsigned long long g_binbuf[MAXB][BINBUF];
__device__ float4             g_boxes[MAXB][TOPK];
__device__ float              g_area[MAXB][TOPK];
__device__ unsigned long long g_mask[MAXB][TOPK * 32];
__device__ unsigned int       g_rowmask[MAXB][64];   // per word-block occupancy

__device__ __forceinline__ unsigned long long make_key(unsigned int bits, int i) {
    return ((unsigned long long)bits << 20) |
           (unsigned long long)(0xFFFFFu - (unsigned int)i);
}

// ---------------- hist over score bits + last-block resolve (ILP-8) ---------
__global__ void hist_pass(const float4* __restrict__ probs4, int N2) {
    __shared__ unsigned int sh[NBINS];
    __shared__ unsigned int s_scan[256];
    __shared__ unsigned int s_bin, s_need, s_last;
    int b = blockIdx.y;
    for (int i = threadIdx.x; i < NBINS; i += blockDim.x) sh[i] = 0;
    __syncthreads();
    const float4* p = probs4 + (size_t)b * N2;
    int stride = gridDim.x * blockDim.x;
    int i0 = blockIdx.x * blockDim.x + threadIdx.x;
    for (int i = i0; i < N2; i += 8 * stride) {
        float4 v[8]; bool ok[8];
        #pragma unroll
        for (int s = 0; s < 8; s++) {
            int ii = i + s * stride;
            ok[s] = ii < N2;
            v[s] = __ldg(p + (ok[s] ? ii : 0));
        }
        #pragma unroll
        for (int s = 0; s < 8; s++) {
            if (ok[s]) {
                atomicAdd(&sh[__float_as_uint(v[s].y) >> 19], 1u);
                atomicAdd(&sh[__float_as_uint(v[s].w) >> 19], 1u);
            }
        }
    }
    __syncthreads();
    for (int i = threadIdx.x; i < NBINS; i += blockDim.x)
        if (sh[i]) atomicAdd(&g_hist[b][i], sh[i]);

    __threadfence();
    __syncthreads();
    if (threadIdx.x == 0) {
        unsigned int ticket = atomicAdd(&g_done[b], 1u);
        s_last = (ticket == gridDim.x - 1) ? 1u : 0u;
    }
    __syncthreads();
    if (!s_last) return;
    __threadfence();

    int t = threadIdx.x;   // 256
    int base = NBINS - 1 - t * 32;
    unsigned int cnts[32];
    unsigned int sum = 0;
    #pragma unroll
    for (int m = 0; m < 32; m++) { cnts[m] = g_hist[b][base - m]; sum += cnts[m]; }
    s_scan[t] = sum;
    __syncthreads();
    for (int off = 1; off < 256; off <<= 1) {
        unsigned int v = (t >= off) ? s_scan[t - off] : 0u;
        __syncthreads();
        s_scan[t] += v;
        __syncthreads();
    }
    const unsigned int k = TOPK;
    unsigned int incl = s_scan[t];
    unsigned int excl = incl - sum;
    if (excl < k && k <= incl) {
        unsigned int cum = excl;
        #pragma unroll
        for (int m = 0; m < 32; m++) {
            if (cum + cnts[m] >= k) { s_bin = (unsigned int)(base - m);
                                      s_need = k - cum; break; }
            cum += cnts[m];
        }
    }
    __syncthreads();
    if (t == 0) {
        g_bin[b]  = s_bin;
        g_need[b] = s_need;
        g_cnt[b]  = 0;
        g_bcnt[b] = 0;
        g_done[b] = 0;
    }
    #pragma unroll
    for (int m = 0; m < 32; m++) g_hist[b][base - m] = 0;
}

// ---------------- warp-aggregated append ------------------------------------
__device__ __forceinline__ int warp_append(int* counter, bool pred) {
    unsigned int bal = __ballot_sync(0xFFFFFFFFu, pred);
    int n = __popc(bal);
    int base = 0;
    if (n) {
        int leader = __ffs(bal) - 1;
        if ((int)(threadIdx.x & 31) == leader) base = atomicAdd(counter, n);
        base = __shfl_sync(0xFFFFFFFFu, base, leader);
    }
    return base + __popc(bal & ((1u << (threadIdx.x & 31)) - 1u));
}

// ------- fused: partition (all blocks) + exact refine+sort+decode (last) ----
__global__ void __launch_bounds__(1024)
partition_refine_sort(const float4* __restrict__ probs4, int N2,
                      const float4* __restrict__ bbox,
                      const float4* __restrict__ anchors, int N) {
    __shared__ unsigned long long sk[SORTN];     // 16 KB sort array
    __shared__ unsigned int shist[NBINS];        // 32 KB refine hist
    __shared__ unsigned int s_warp[32];
    __shared__ unsigned int s_bin, s_need, s_last;
    __shared__ int s_cnt;

    int b = blockIdx.y;
    int t = threadIdx.x;      // 1024
    int lane = t & 31, wid = t >> 5;

    // ---- phase A: partition scan (ILP-8) ----
    {
        unsigned int Tbin = g_bin[b];
        const float4* p = probs4 + (size_t)b * N2;
        int stride = gridDim.x * blockDim.x;
        int i0 = blockIdx.x * blockDim.x + t;
        for (int i = i0; i < N2; i += 8 * stride) {
            float4 v[8]; bool ok[8]; int iic[8];
            #pragma unroll
            for (int s = 0; s < 8; s++) {
                int ii = i + s * stride;
                ok[s] = ii < N2;
                iic[s] = ok[s] ? ii : 0;
                v[s] = __ldg(p + iic[s]);
            }
            #pragma unroll
            for (int s = 0; s < 8; s++) {
                unsigned int b0 = __float_as_uint(v[s].y);
                unsigned int b1 = __float_as_uint(v[s].w);
                unsigned int bin0 = b0 >> 19, bin1 = b1 >> 19;

                bool c0 = ok[s] && (bin0 > Tbin);
                int pos = warp_append(&g_cnt[b], c0);
                if (c0 && pos < CAND) g_cand[b][pos] = make_key(b0, 2 * iic[s]);

                bool d0 = ok[s] && (bin0 == Tbin);
                pos = warp_append(&g_bcnt[b], d0);
                if (d0 && pos < BINBUF) g_binbuf[b][pos] = make_key(b0, 2 * iic[s]);

                bool c1 = ok[s] && (bin1 > Tbin);
                pos = warp_append(&g_cnt[b], c1);
                if (c1 && pos < CAND) g_cand[b][pos] = make_key(b1, 2 * iic[s] + 1);

                bool d1 = ok[s] && (bin1 == Tbin);
                pos = warp_append(&g_bcnt[b], d1);
                if (d1 && pos < BINBUF) g_binbuf[b][pos] = make_key(b1, 2 * iic[s] + 1);
            }
        }
    }

    // ---- ticket: last block of this batch continues ----
    __threadfence();
    __syncthreads();
    if (t == 0) {
        unsigned int ticket = atomicAdd(&g_done2[b], 1u);
        s_last = (ticket == gridDim.x - 1) ? 1u : 0u;
    }
    __syncthreads();
    if (!s_last) return;
    __threadfence();

    int n = g_bcnt[b];    if (n > BINBUF) n = BINBUF;
    int acnt = g_cnt[b];  if (acnt > CAND) acnt = CAND;
    if (t == 0) { g_done2[b] = 0; s_need = g_need[b]; }
    __syncthreads();

    // ---- phase B: 3-pass exact refine over low 39 key bits ----
    const unsigned long long M39 = (1ULL << 39) - 1ULL;
    unsigned long long prefix = 0ULL;
    for (int pass = 0; pass < 3; pass++) {
        int shift = 26 - 13 * pass;
        for (int i = t; i < NBINS; i += 1024) shist[i] = 0;
        __syncthreads();
        for (int i = t; i < n; i += 1024) {
            unsigned long long k39 = g_binbuf[b][i] & M39;
            if ((k39 >> (shift + 13)) == prefix)
                atomicAdd(&shist[(unsigned int)(k39 >> shift) & (NBINS - 1)], 1u);
        }
        __syncthreads();
        int base = NBINS - 1 - t * 8;
        unsigned int c8[8];
        unsigned int sum = 0;
        #pragma unroll
        for (int m = 0; m < 8; m++) { c8[m] = shist[base - m]; sum += c8[m]; }
        unsigned int v = sum;
        #pragma unroll
        for (int off = 1; off < 32; off <<= 1) {
            unsigned int u = __shfl_up_sync(0xFFFFFFFFu, v, off);
            if (lane >= off) v += u;
        }
        if (lane == 31) s_warp[wid] = v;
        __syncthreads();
        if (wid == 0) {
            unsigned int w = s_warp[lane];
            #pragma unroll
            for (int off = 1; off < 32; off <<= 1) {
                unsigned int u = __shfl_up_sync(0xFFFFFFFFu, w, off);
                if (lane >= off) w += u;
            }
            s_warp[lane] = w;
        }
        __syncthreads();
        unsigned int need = s_need;
        unsigned int woff = (wid > 0) ? s_warp[wid - 1] : 0u;
        unsigned int incl = v + woff;
        unsigned int excl = incl - sum;
        if (excl < need && need <= incl) {
            unsigned int cum = excl;
            #pragma unroll
            for (int m = 0; m < 8; m++) {
                if (cum + c8[m] >= need) {
                    s_bin  = (unsigned int)(base - m);
                    s_need = need - cum;
                    break;
                }
                cum += c8[m];
            }
        }
        __syncthreads();
        prefix = (prefix << 13) | (unsigned long long)s_bin;
        __syncthreads();
    }
    unsigned long long thr = prefix;

    // ---- phase C: build exactly-2048 sort array ----
    for (int i = t; i < SORTN; i += 1024) sk[i] = 0ULL;
    if (t == 0) s_cnt = acnt;
    __syncthreads();
    for (int i = t; i < acnt; i += 1024) sk[i] = g_cand[b][i];
    int npad = ((n + 1023) / 1024) * 1024;
    for (int i = t; i < npad; i += 1024) {
        bool ok = i < n;
        unsigned long long kk = ok ? g_binbuf[b][i] : 0ULL;
        bool pred = ok && ((kk & M39) >= thr);
        int pos = warp_append(&s_cnt, pred);
        if (pred && pos < SORTN) sk[pos] = kk;
    }
    __syncthreads();

    // ---- phase D: bitonic sort 2048 ----
    for (int k = 2; k <= SORTN; k <<= 1) {
        for (int j = k >> 1; j > 0; j >>= 1) {
            #pragma unroll
            for (int s = 0; s < 2; s++) {
                int i = t + s * 1024;
                int l = i ^ j;
                if (l > i) {
                    bool up = ((i & k) == 0);
                    unsigned long long a = sk[i], c = sk[l];
                    if ((a > c) == up) { sk[i] = c; sk[l] = a; }
                }
            }
            __syncthreads();
        }
    }

    // ---- phase E: decode top 2048 ----
    const float4* bb = bbox    + (size_t)b * N;
    const float4* an = anchors + (size_t)b * N;
    #pragma unroll
    for (int s = 0; s < 2; s++) {
        int r = t + s * 1024;
        unsigned long long key = sk[SORTN - 1 - r];
        int idx = 0xFFFFF - (int)(key & 0xFFFFFULL);
        float4 a = an[idx];
        float4 d = bb[idx];
        float d0 = __fmul_rn(d.x, 0.1f), d1 = __fmul_rn(d.y, 0.1f);
        float d2 = __fmul_rn(d.z, 0.2f), d3 = __fmul_rn(d.w, 0.2f);
        float h = __fsub_rn(a.z, a.x);
        float w = __fsub_rn(a.w, a.y);
        float cy = __fadd_rn(__fadd_rn(a.x, __fmul_rn(0.5f, h)), __fmul_rn(d0, h));
        float cx = __fadd_rn(__fadd_rn(a.y, __fmul_rn(0.5f, w)), __fmul_rn(d1, w));
        float e2 = (float)exp((double)d2);
        float e3 = (float)exp((double)d3);
        float h2 = __fmul_rn(h, e2);
        float w2 = __fmul_rn(w, e3);
        float y1 = __fsub_rn(cy, __fmul_rn(0.5f, h2));
        float x1 = __fsub_rn(cx, __fmul_rn(0.5f, w2));
        float y2 = __fadd_rn(cy, __fmul_rn(0.5f, h2));
        float x2 = __fadd_rn(cx, __fmul_rn(0.5f, w2));
        y1 = fminf(fmaxf(y1, 0.0f), 1.0f);
        x1 = fminf(fmaxf(x1, 0.0f), 1.0f);
        y2 = fminf(fmaxf(y2, 0.0f), 1.0f);
        x2 = fminf(fmaxf(x2, 0.0f), 1.0f);
        g_boxes[b][r] = make_float4(y1, x1, y2, x2);
        g_area[b][r]  = __fmul_rn(__fsub_rn(y2, y1), __fsub_rn(x2, x1));
    }
}

// ---------------- pairwise IoU > 0.7 bitmask + diag row-occupancy -----------
__global__ void mask_kernel() {
    int b = blockIdx.y;
    int tt = blockIdx.x;
    int ib = 0, acc = 0;
    while (acc + (32 - ib) <= tt) { acc += 32 - ib; ib++; }
    int jb = ib + (tt - acc);

    __shared__ float4 sj[64];
    __shared__ float  sa[64];
    int t = threadIdx.x;   // 64
    sj[t] = g_boxes[b][jb * 64 + t];
    sa[t] = g_area[b][jb * 64 + t];
    __syncthreads();
    int i = ib * 64 + t;
    float4 bi = g_boxes[b][i];
    float areai = g_area[b][i];
    unsigned long long bits = 0ULL;
    #pragma unroll 8
    for (int jj = 0; jj < 64; jj++) {
        float4 bj = sj[jj];
        float ih = fmaxf(__fsub_rn(fminf(bi.z, bj.z), fmaxf(bi.x, bj.x)), 0.0f);
        float iw = fmaxf(__fsub_rn(fminf(bi.w, bj.w), fmaxf(bi.y, bj.y)), 0.0f);
        float inter = __fmul_rn(ih, iw);
        float uni = __fsub_rn(__fadd_rn(areai, sa[jj]), inter);
        float den = __fadd_rn(uni, 1e-8f);
        if (inter > 0.68f * den) {            // conservative prefilter
            float iou = __fdiv_rn(inter, den);
            if (iou > 0.7f) bits |= (1ULL << jj);
        }
    }
    g_mask[b][(size_t)i * 32 + jb] = bits;

    // diag blocks: record which rows have a nonzero premasked word
    // (row t can only suppress strictly-later bits)
    unsigned long long prem = bits & ((t < 63) ? (~0ULL << (t + 1)) : 0ULL);
    unsigned int flag = (ib == jb && prem != 0ULL) ? 1u : 0u;
    unsigned int bal = __ballot_sync(0xFFFFFFFFu, flag != 0u);
    if (ib == jb && (t & 31) == 0)
        g_rowmask[b][ib * 2 + (t >> 5)] = bal;   // halves: rows 0-31 / 32-63
}

// ------- one-warp NMS: sparse ffs chain + EARLY EXIT at NPROP kept ----------
__global__ void __launch_bounds__(32) nms_kernel(float* __restrict__ out) {
    int b = blockIdx.x;
    int t = threadIdx.x;   // 32 (one warp)
    __shared__ unsigned long long sbuf[2][2048];   // 2 x 16KB mask blocks
    __shared__ unsigned long long srm[32];         // per-block row-occupancy

    float4* o4 = (float4*)(out + (size_t)b * NPROP * 4);
    for (int k = t; k < NPROP; k += 32) o4[k] = make_float4(0.f, 0.f, 0.f, 0.f);

    const unsigned long long* mb = g_mask[b];

    // stage rowmask (32 u64 from 64 u32 halves)
    {
        unsigned int lo = g_rowmask[b][t * 2];
        unsigned int hi = g_rowmask[b][t * 2 + 1];
        srm[t] = ((unsigned long long)hi << 32) | lo;
    }

    {   // prefetch block 0
        const char* src = (const char*)mb;
        char* dst = (char*)&sbuf[0][0];
        #pragma unroll
        for (int k = 0; k < 32; k++) {
            unsigned int d = (unsigned int)__cvta_generic_to_shared(dst + t * 16 + k * 512);
            asm volatile("cp.async.cg.shared.global [%0], [%1], 16;\n"
                         :: "r"(d), "l"(src + t * 16 + k * 512));
        }
        asm volatile("cp.async.commit_group;\n" ::);
    }

    unsigned long long keepw = ~0ULL;      // lane t owns bits [t*64, t*64+64)
    int total = 0;                         // kept among FINALIZED words

    for (int c = 0; c < 32; c++) {
        int cb = c & 1;
        asm volatile("cp.async.wait_group 0;\n" ::);
        __syncwarp();

        if (c + 1 < 32) {   // prefetch next block
            const char* src = (const char*)(mb + (size_t)(c + 1) * 2048);
            char* dst = (char*)&sbuf[cb ^ 1][0];
            #pragma unroll
            for (int k = 0; k < 32; k++) {
                unsigned int d = (unsigned int)__cvta_generic_to_shared(dst + t * 16 + k * 512);
                asm volatile("cp.async.cg.shared.global [%0], [%1], 16;\n"
                             :: "r"(d), "l"(src + t * 16 + k * 512));
            }
            asm volatile("cp.async.commit_group;\n" ::);
        }

        const unsigned long long* blk = &sbuf[cb][0];

        // ---- sparse within-word chain (all lanes redundant, uniform) ----
        unsigned long long cur = __shfl_sync(0xFFFFFFFFu, keepw, c);
        unsigned long long w = cur & srm[c];
        while (w) {
            int bit = __ffsll((long long)w) - 1;
            w &= w - 1;                                   // pop processed bit
            unsigned long long hi = (bit < 63) ? (~0ULL << (bit + 1)) : 0ULL;
            unsigned long long m = blk[bit * 32 + c] & hi;  // LDS broadcast
            cur &= ~m;                                    // suppress later bits
            w &= cur;                                     // drop suppressed
        }
        // cur identical on all lanes (uniform data, uniform control)

        if (t == c) keepw = cur;          // word c is now FINAL
        total += __popcll(cur);           // uniform across lanes

        // early exit: every later bit has rank >= total >= NPROP — its keep
        // flag cannot affect the output (suppression is strictly forward)
        if (total >= NPROP) break;

        // ---- cross-word suppression: lane t's own column, 4 accumulators ---
        unsigned long long s0 = 0ULL, s1 = 0ULL, s2 = 0ULL, s3 = 0ULL;
        #pragma unroll
        for (int r = 0; r < 64; r += 4) {
            unsigned long long e0 =
                (unsigned long long)((long long)(cur << (63 - r)) >> 63);
            unsigned long long e1 =
                (unsigned long long)((long long)(cur << (62 - r)) >> 63);
            unsigned long long e2 =
                (unsigned long long)((long long)(cur << (61 - r)) >> 63);
            unsigned long long e3 =
                (unsigned long long)((long long)(cur << (60 - r)) >> 63);
            s0 |= blk[(r + 0) * 32 + t] & e0;
            s1 |= blk[(r + 1) * 32 + t] & e1;
            s2 |= blk[(r + 2) * 32 + t] & e2;
            s3 |= blk[(r + 3) * 32 + t] & e3;
        }
        unsigned long long supp = (s0 | s1) | (s2 | s3);

        if (t > c) keepw &= ~supp;
        __syncwarp();
    }

    // exclusive prefix of popcounts across lanes.
    // Lanes beyond the stop word may hold unfinalized keepw, but their
    // exclusive prefix >= total >= NPROP, so rank<NPROP filters them exactly.
    int pc = __popcll(keepw);
    int ex = pc;
    #pragma unroll
    for (int off = 1; off < 32; off <<= 1) {
        int v = __shfl_up_sync(0xFFFFFFFFu, ex, off);
        if (t >= off) ex += v;
    }
    ex -= pc;

    for (int bit = 0; bit < 64; bit++) {
        if ((keepw >> bit) & 1ULL) {
            unsigned long long lower = (bit > 0) ? (keepw & ((1ULL << bit) - 1ULL)) : 0ULL;
            int rank = ex + __popcll(lower);
            if (rank < NPROP) {
                float4 bx = g_boxes[b][t * 64 + bit];
                float* o = out + ((size_t)b * NPROP + rank) * 4;
                o[0] = bx.x; o[1] = bx.y; o[2] = bx.z; o[3] = bx.w;
            }
        }
    }
}

// ---------------- launch ----------------------------------------------------
extern "C" void kernel_launch(void* const* d_in, const int* in_sizes, int n_in,
                              void* d_out, int out_size) {
    const float4* probs4  = (const float4*)d_in[0];
    const float4* bbox    = (const float4*)d_in[1];
    const float4* anchors = (const float4*)d_in[2];
    float* out = (float*)d_out;

    int B = out_size / (NPROP * 4);
    if (B < 1) B = 1;
    if (B > MAXB) B = MAXB;
    int N  = in_sizes[0] / (2 * B);
    int N2 = N / 2;

    hist_pass<<<dim3(256, B), 256>>>(probs4, N2);
    partition_refine_sort<<<dim3(64, B), 1024>>>(probs4, N2, bbox, anchors, N);
    mask_kernel<<<dim3(TILES, B), 64>>>();
    nms_kernel<<<B, 32>>>(out);
}